// round 9
// baseline (speedup 1.0000x reference)
#include <cuda_runtime.h>
#include <cuda_bf16.h>
#include <math.h>

#define BB 4
#define CIN 3
#define CC 32
#define HH 256
#define WW 256
#define MM 16
#define NB 4
#define OC 4
#define PIX (HH*WW)
#define GSTR 260
#define HSTR 258

typedef unsigned long long ull;

__device__ __forceinline__ ull pk2(float lo, float hi) {
    ull r; asm("mov.b64 %0,{%1,%2};" : "=l"(r) : "f"(lo), "f"(hi)); return r;
}
__device__ __forceinline__ void up2(ull v, float& a, float& b) {
    asm("mov.b64 {%0,%1},%2;" : "=f"(a), "=f"(b) : "l"(v));
}
__device__ __forceinline__ ull fma2(ull a, ull b, ull c) {
    ull d; asm("fma.rn.f32x2 %0,%1,%2,%3;" : "=l"(d) : "l"(a), "l"(b), "l"(c)); return d;
}
__device__ __forceinline__ ull mul2(ull a, ull b) {
    ull d; asm("mul.rn.f32x2 %0,%1,%2;" : "=l"(d) : "l"(a), "l"(b)); return d;
}
__device__ __forceinline__ ull neg2(ull a) { return a ^ 0x8000000080000000ULL; }

__device__ __forceinline__ float gelu1(float v) {
    return 0.5f * v * (1.f + erff(v * 0.70710678118654752f));
}

// Scratch (device globals: allocation-free)
__device__ float  g_x0[BB*CC*PIX];
__device__ float  g_xa[OC*BB*CC*PIX];
__device__ float  g_xb[OC*BB*CC*PIX];
__device__ float2 g_S [OC*BB*MM*HH*CC];            // [boh][m][h][c]
__device__ float2 g_X [OC*BB*CC*MM*MM];
__device__ float2 g_X0[BB*CC*MM*MM];
__device__ float2 g_Y [OC*BB*CC*MM*MM];
__device__ float2 g_W [OC*NB*MM*MM*CC*CC];         // [ohn][kl][c][o]
__device__ float2 g_tw2[256];
__device__ ulonglong2 g_twd[16 * 64];              // [m][w2] -> (cos pk2, sin pk2) at w=2*w2, 2*w2+1

__global__ void init_tw() {
    int t = threadIdx.x;
    double a = 6.283185307179586476925286766559 * (double)t / 256.0;
    g_tw2[t] = make_float2((float)cos(a), (float)sin(a));
}

__global__ void init_twd() {
    int idx = blockIdx.x * 256 + threadIdx.x;      // 1024 entries
    int m = idx >> 6, w2 = idx & 63;
    double th = 6.283185307179586476925286766559 / 256.0;
    double a0 = th * (double)(m * (2 * w2));
    double a1 = th * (double)(m * (2 * w2 + 1));
    g_twd[idx] = make_ulonglong2(pk2((float)cos(a0), (float)cos(a1)),
                                 pk2((float)sin(a0), (float)sin(a1)));
}

__global__ void init_w(const float* __restrict__ wr, const float* __restrict__ wi) {
    long d = (long)blockIdx.x * blockDim.x + threadIdx.x;
    int o   = (int)(d & 31);
    int c   = (int)((d >> 5) & 31);
    int kl  = (int)((d >> 10) & 255);
    int ohn = (int)(d >> 18);
    int k = kl >> 4, l = kl & 15;
    long s = ((((long)ohn * 32 + c) * 32 + o) * 16 + k) * 16 + l;
    g_W[d] = make_float2(wr[s], wi[s]);
}

__global__ void klift(const float* __restrict__ x, const float* __restrict__ lw,
                      const float* __restrict__ lb) {
    int idx = blockIdx.x * 256 + threadIdx.x;
    int pix = idx & (PIX - 1);
    int bc  = idx >> 16;
    int c = bc & 31, b = bc >> 5;
    float acc = lb[c];
    #pragma unroll
    for (int i = 0; i < CIN; i++)
        acc = fmaf(x[(b * CIN + i) * PIX + pix], lw[c * CIN + i], acc);
    g_x0[idx] = acc;
}

// K1 (once): packed W-axis truncated DFT of x0 -> S[b][m][h][c]
__global__ void k1(const float* __restrict__ xin) {
    __shared__ __align__(16) float xs[32 * GSTR];
    __shared__ float2 tws[256];
    int row0 = blockIdx.x * 32;
    for (int i = threadIdx.x; i < 8192; i += 256)
        xs[(i >> 8) * GSTR + (i & 255)] = xin[(long)row0 * 256 + i];
    tws[threadIdx.x] = g_tw2[threadIdx.x];
    __syncthreads();
    int b = row0 >> 13, c = (row0 >> 8) & 31, h0 = row0 & 255;
    int m = threadIdx.x >> 4, hh = threadIdx.x & 15;
    float sgn = (m & 1) ? -1.f : 1.f;
    ull sgn2 = pk2(sgn, sgn);
    float2 tm = tws[m], st = tws[(2 * m) & 255];
    ull cs = pk2(st.x, st.x), ss = pk2(st.y, st.y), nss = neg2(ss);
    ull c0 = pk2(1.f, tm.x), s0 = pk2(0.f, tm.y);
    ull arA = 0, asA = 0, arB = 0, asB = 0;
    const float* xr0 = xs + hh * GSTR;
    const float* xr1 = xs + (hh + 16) * GSTR;
    #pragma unroll 4
    for (int w = 0; w < 128; w += 2) {
        ull A0 = *(const ull*)(xr0 + w), B0 = *(const ull*)(xr0 + w + 128);
        ull A1 = *(const ull*)(xr1 + w), B1 = *(const ull*)(xr1 + w + 128);
        ull u0 = fma2(sgn2, B0, A0), u1 = fma2(sgn2, B1, A1);
        arA = fma2(u0, c0, arA); asA = fma2(u0, s0, asA);
        arB = fma2(u1, c0, arB); asB = fma2(u1, s0, asB);
        ull cn = fma2(c0, cs, mul2(s0, nss));
        s0 = fma2(s0, cs, mul2(c0, ss)); c0 = cn;
    }
    float a, q;
    up2(arA, a, q); float ar = a + q; up2(asA, a, q); float ai = -(a + q);
    g_S[(((long)(b * 16 + m) * 256) + h0 + hh) * 32 + c] = make_float2(ar, ai);
    up2(arB, a, q); ar = a + q; up2(asB, a, q); ai = -(a + q);
    g_S[(((long)(b * 16 + m) * 256) + h0 + hh + 16) * 32 + c] = make_float2(ar, ai);
}

// K2a: packed H-axis truncated DFT (+1/256). grid(16 l, ng, 2 chalf), 256 thr.
__global__ void k2a(const float2* __restrict__ S, float2* __restrict__ X) {
    __shared__ __align__(16) float Sre[16 * HSTR];
    __shared__ __align__(16) float Sim[16 * HSTR];
    __shared__ float2 tws[256];
    int l = blockIdx.x, g = blockIdx.y, ch = blockIdx.z;
    const float2* Sp = S + ((long)(g * 16 + l) * 256) * 32 + ch * 16;
    for (int i = threadIdx.x; i < 4096; i += 256) {
        int hh = i >> 4, cc = i & 15;
        float2 v = Sp[hh * 32 + cc];
        Sre[cc * HSTR + hh] = v.x; Sim[cc * HSTR + hh] = v.y;
    }
    tws[threadIdx.x] = g_tw2[threadIdx.x];
    __syncthreads();
    int c16 = threadIdx.x & 15, k = threadIdx.x >> 4;
    float sgn = (k & 1) ? -1.f : 1.f;
    ull sgn2 = pk2(sgn, sgn);
    float2 tk = tws[k], st = tws[(2 * k) & 255];
    ull cs = pk2(st.x, st.x), ss = pk2(st.y, st.y), nss = neg2(ss);
    ull c0 = pk2(1.f, tk.x), s0 = pk2(0.f, tk.y);
    ull arA = 0, arB = 0, aiA = 0, aiB = 0;
    const float* re = Sre + c16 * HSTR;
    const float* im = Sim + c16 * HSTR;
    #pragma unroll 4
    for (int hq = 0; hq < 128; hq += 2) {
        ull rA = *(const ull*)(re + hq), rB = *(const ull*)(re + hq + 128);
        ull iA = *(const ull*)(im + hq), iB = *(const ull*)(im + hq + 128);
        ull ux = fma2(sgn2, rB, rA), uy = fma2(sgn2, iB, iA);
        arA = fma2(ux, c0, arA); arB = fma2(uy, s0, arB);
        aiA = fma2(uy, c0, aiA); aiB = fma2(ux, s0, aiB);
        ull cn = fma2(c0, cs, mul2(s0, nss));
        s0 = fma2(s0, cs, mul2(c0, ss)); c0 = cn;
    }
    float a, q;
    up2(arA, a, q); float ar = a + q; up2(arB, a, q); ar += a + q;
    up2(aiA, a, q); float ai = a + q; up2(aiB, a, q); ai -= a + q;
    X[((long)(g * 32 + ch * 16 + c16)) * 256 + k * 16 + l] =
        make_float2(ar * (1.f / 256.f), ai * (1.f / 256.f));
}

// K2b: channel mix. grid(256 kl, OC oh), 128 thr.
__global__ void k2b(const float2* __restrict__ X, int x_oh_mult, int n) {
    __shared__ float2 Ws[32 * 32];
    __shared__ float2 Xs[4][32];
    int kl = blockIdx.x, oh = blockIdx.y;
    const float2* Wt = g_W + ((long)(oh * NB + n) * 256 + kl) * 1024;
    for (int i = threadIdx.x; i < 1024; i += 128) Ws[i] = Wt[i];
    {
        int b = threadIdx.x >> 5, c = threadIdx.x & 31;
        Xs[b][c] = X[((long)((oh * x_oh_mult + b) * 32 + c)) * 256 + kl];
    }
    __syncthreads();
    int b = threadIdx.x >> 5, o = threadIdx.x & 31;
    float yr = 0.f, yi = 0.f;
    #pragma unroll
    for (int c0 = 0; c0 < 32; c0++) {
        float2 xv = Xs[b][c0];
        float2 wv = Ws[c0 * 32 + o];
        yr += xv.x * wv.x - xv.y * wv.y;
        yi += xv.x * wv.y + xv.y * wv.x;
    }
    g_Y[((long)((oh * 4 + b) * 32 + o)) * 256 + kl] = make_float2(yr, yi);
}

// K3: H-inverse + packed W-inverse + packed bypass + GELU,
// then (LAST ? projection : next-iteration table-driven packed W-DFT)
// Dynamic smem layout (68224 B):
//   gs    [0,      33280)  float  32*GSTR
//   Bs2   [33280,  41472)  ulonglong2 32*16
//   bwT2  [41472,  49664)  ull 32*32
//   twds  [49664,  66048)  ulonglong2 16*64
//   tws   [66048,  68096)  float2 256
//   pws   [68096,  68224)  float 32
#define SMEM_K3 68224
template <bool LAST>
__global__ void __launch_bounds__(256, 3) k3(
    const float* __restrict__ xin, int in_nb, float* __restrict__ xout,
    const float* __restrict__ byp_w, const float* __restrict__ byp_b,
    const float* __restrict__ pw, const float* __restrict__ pb, int n) {
    extern __shared__ __align__(16) char smemraw[];
    float*      gs   = (float*)smemraw;
    ulonglong2* Bs2  = (ulonglong2*)(smemraw + 33280);
    ull*        bwT2 = (ull*)(smemraw + 41472);
    ulonglong2* twds = (ulonglong2*)(smemraw + 49664);
    float2*     tws  = (float2*)(smemraw + 66048);
    float*      pws  = (float*)(smemraw + 68096);

    int h = blockIdx.x, boh = blockIdx.y;
    int b = boh & 3, oh = boh >> 2;
    int ohn = oh * NB + n;
    int t = threadIdx.x;

    tws[t] = g_tw2[t];
    {   // bypass weights [o][i] -> [i][o], replicated f32x2 packs
        const float* bwp = byp_w + ohn * 1024;
        #pragma unroll
        for (int r = 0; r < 4; r++) {
            int idx = t + r * 256;
            float v = bwp[idx];
            bwT2[(idx & 31) * 32 + (idx >> 5)] = pk2(v, v);
        }
    }
    if (!LAST) {
        #pragma unroll
        for (int r = 0; r < 4; r++)
            twds[t + r * 256] = g_twd[t + r * 256];
    }
    if (LAST && t < 32) pws[t] = pw[t];
    __syncthreads();

    // Phase B: H-inverse of Y; store scaled, imag-negated, replicated
    {
        const float* bbp = byp_b + ohn * 32;
        const float2* Yb = g_Y + (long)boh * 8192;
        #pragma unroll
        for (int rep = 0; rep < 2; rep++) {
            int idx = t + rep * 256;
            int o = idx >> 4, l = idx & 15;
            float br = 0.f, bi = 0.f;
            #pragma unroll
            for (int k = 0; k < 16; k++) {
                float2 y = Yb[o * 256 + k * 16 + l];
                float2 tw = tws[(k * h) & 255];
                br += y.x * tw.x - y.y * tw.y;
                bi += y.x * tw.y + y.y * tw.x;
            }
            float sc = (l == 0) ? (1.f / 256.f) : (2.f / 256.f);
            br *= sc; bi *= -sc;
            if (l == 0) br += bbp[o];          // fold bias; DC imag dropped (C2R)
            Bs2[idx] = make_ulonglong2(pk2(br, br), pk2(bi, bi));
        }
    }
    __syncthreads();

    // Phase C: thread = (og, wg): 8 o x 4 w register tile, f32x2 packed
    {
        int wg = t & 63, og = t >> 6;
        int w0 = wg * 4, o0 = og * 8;
        float2 t0 = tws[w0], t1 = tws[w0 + 1], t2 = tws[w0 + 2], t3 = tws[w0 + 3];
        ull csA = pk2(t0.x, t1.x), ssA = pk2(t0.y, t1.y), nssA = neg2(ssA);
        ull csB = pk2(t2.x, t3.x), ssB = pk2(t2.y, t3.y), nssB = neg2(ssB);
        ull accA[8], accB[8];
        #pragma unroll
        for (int oo = 0; oo < 8; oo++) {
            ull v = Bs2[(o0 + oo) * 16].x;
            accA[oo] = v; accB[oo] = v;
        }
        // spectral sum over l (trig by packed recurrence)
        ull cA = csA, sA = ssA, cB = csB, sB = ssB;
        #pragma unroll 5
        for (int l = 1; l < 16; l++) {
            #pragma unroll
            for (int oo = 0; oo < 8; oo++) {
                ulonglong2 Bv = Bs2[(o0 + oo) * 16 + l];
                accA[oo] = fma2(Bv.x, cA, accA[oo]);
                accA[oo] = fma2(Bv.y, sA, accA[oo]);
                accB[oo] = fma2(Bv.x, cB, accB[oo]);
                accB[oo] = fma2(Bv.y, sB, accB[oo]);
            }
            ull cn = fma2(cA, csA, mul2(sA, nssA));
            sA = fma2(sA, csA, mul2(cA, ssA)); cA = cn;
            cn = fma2(cB, csB, mul2(sB, nssB));
            sB = fma2(sB, csB, mul2(cB, ssB)); cB = cn;
        }
        // bypass conv: x via coalesced LDG.128, weights via broadcast LDS.128
        int inb = (in_nb == 4) ? b : boh;
        const float* xrow = xin + (((long)inb * 32) << 16) + (h << 8) + w0;
        #pragma unroll 8
        for (int i = 0; i < 32; i++) {
            float4 xv = *(const float4*)(xrow + ((long)i << 16));
            ull xA = pk2(xv.x, xv.y), xB = pk2(xv.z, xv.w);
            const ulonglong2* wp = (const ulonglong2*)(bwT2 + i * 32 + o0);
            ulonglong2 wq0 = wp[0], wq1 = wp[1], wq2 = wp[2], wq3 = wp[3];
            accA[0] = fma2(wq0.x, xA, accA[0]); accB[0] = fma2(wq0.x, xB, accB[0]);
            accA[1] = fma2(wq0.y, xA, accA[1]); accB[1] = fma2(wq0.y, xB, accB[1]);
            accA[2] = fma2(wq1.x, xA, accA[2]); accB[2] = fma2(wq1.x, xB, accB[2]);
            accA[3] = fma2(wq1.y, xA, accA[3]); accB[3] = fma2(wq1.y, xB, accB[3]);
            accA[4] = fma2(wq2.x, xA, accA[4]); accB[4] = fma2(wq2.x, xB, accB[4]);
            accA[5] = fma2(wq2.y, xA, accA[5]); accB[5] = fma2(wq2.y, xB, accB[5]);
            accA[6] = fma2(wq3.x, xA, accA[6]); accB[6] = fma2(wq3.x, xB, accB[6]);
            accA[7] = fma2(wq3.y, xA, accA[7]); accB[7] = fma2(wq3.y, xB, accB[7]);
        }
        // GELU + stores
        #pragma unroll
        for (int oo = 0; oo < 8; oo++) {
            float v0, v1, v2, v3;
            up2(accA[oo], v0, v1); up2(accB[oo], v2, v3);
            float4 gv = make_float4(gelu1(v0), gelu1(v1), gelu1(v2), gelu1(v3));
            *(float4*)(gs + (o0 + oo) * GSTR + w0) = gv;
            if (!LAST)
                *(float4*)(xout + (((long)(boh * 32 + o0 + oo)) << 16) + (h << 8) + w0) = gv;
        }
    }
    __syncthreads();

    if (!LAST) {
        // Phase D: next-iteration W-DFT via precomputed packed twiddle table
        // (no serial chains; twiddle loads are warp-uniform broadcasts)
        int o = t & 31, mp = t >> 5;                // m = mp, mp+8
        float sgn = (mp & 1) ? -1.f : 1.f;
        ull sgn2 = pk2(sgn, sgn);
        const ulonglong2* tw0 = twds + mp * 64;
        const ulonglong2* tw1 = twds + (mp + 8) * 64;
        ull ar0 = 0, as0 = 0, ar1 = 0, as1 = 0;
        const float* go = gs + o * GSTR;
        #pragma unroll 8
        for (int w2 = 0; w2 < 64; w2++) {
            ull A  = *(const ull*)(go + 2 * w2);
            ull Bv = *(const ull*)(go + 2 * w2 + 128);
            ull u = fma2(sgn2, Bv, A);
            ulonglong2 tq0 = tw0[w2];
            ulonglong2 tq1 = tw1[w2];
            ar0 = fma2(u, tq0.x, ar0); as0 = fma2(u, tq0.y, as0);
            ar1 = fma2(u, tq1.x, ar1); as1 = fma2(u, tq1.y, as1);
        }
        float a, q;
        up2(ar0, a, q); float ar = a + q; up2(as0, a, q); float ai = -(a + q);
        g_S[(((long)(boh * 16 + mp) * 256) + h) * 32 + o] = make_float2(ar, ai);
        up2(ar1, a, q); ar = a + q; up2(as1, a, q); ai = -(a + q);
        g_S[(((long)(boh * 16 + mp + 8) * 256) + h) * 32 + o] = make_float2(ar, ai);
    } else {
        // projection
        float pacc = 0.f;
        #pragma unroll
        for (int o = 0; o < 32; o++)
            pacc = fmaf(gs[o * GSTR + t], pws[o], pacc);
        xout[(((long)(b * OC + oh) * 256 + h) << 8) + t] = pacc + pb[0];
    }
}

extern "C" void kernel_launch(void* const* d_in, const int* in_sizes, int n_in,
                              void* d_out, int out_size) {
    const float* x      = (const float*)d_in[0];
    const float* lift_w = (const float*)d_in[1];
    const float* lift_b = (const float*)d_in[2];
    const float* wr     = (const float*)d_in[3];
    const float* wi     = (const float*)d_in[4];
    const float* byp_w  = (const float*)d_in[5];
    const float* byp_b  = (const float*)d_in[6];
    const float* proj_w = (const float*)d_in[7];
    const float* proj_b = (const float*)d_in[8];
    float* out = (float*)d_out;

    float *x0, *xa, *xb;
    float2 *S, *X, *X0;
    cudaGetSymbolAddress((void**)&x0, g_x0);
    cudaGetSymbolAddress((void**)&xa, g_xa);
    cudaGetSymbolAddress((void**)&xb, g_xb);
    cudaGetSymbolAddress((void**)&S,  g_S);
    cudaGetSymbolAddress((void**)&X,  g_X);
    cudaGetSymbolAddress((void**)&X0, g_X0);

    cudaFuncSetAttribute(k3<false>, cudaFuncAttributeMaxDynamicSharedMemorySize, SMEM_K3);
    cudaFuncSetAttribute(k3<true>,  cudaFuncAttributeMaxDynamicSharedMemorySize, SMEM_K3);

    init_tw<<<1, 256>>>();
    init_twd<<<4, 256>>>();
    init_w<<<4096, 1024>>>(wr, wi);
    klift<<<(BB * CC * PIX) / 256, 256>>>(x, lift_w, lift_b);
    k1<<<1024, 256>>>(x0);                          // S(x0)
    k2a<<<dim3(16, 4, 2), 256>>>(S, X0);            // X(x0), shared across oh

    dim3 g3(256, 16);
    // n = 0 (all oh concurrent)
    k2b<<<dim3(256, OC), 128>>>(X0, 0, 0);
    k3<false><<<g3, 256, SMEM_K3>>>(x0, 4, xa, byp_w, byp_b, proj_w, proj_b, 0);
    // n = 1
    k2a<<<dim3(16, 16, 2), 256>>>(S, X);
    k2b<<<dim3(256, OC), 128>>>(X, 4, 1);
    k3<false><<<g3, 256, SMEM_K3>>>(xa, 16, xb, byp_w, byp_b, proj_w, proj_b, 1);
    // n = 2
    k2a<<<dim3(16, 16, 2), 256>>>(S, X);
    k2b<<<dim3(256, OC), 128>>>(X, 4, 2);
    k3<false><<<g3, 256, SMEM_K3>>>(xb, 16, xa, byp_w, byp_b, proj_w, proj_b, 2);
    // n = 3 (fused projection)
    k2a<<<dim3(16, 16, 2), 256>>>(S, X);
    k2b<<<dim3(256, OC), 128>>>(X, 4, 3);
    k3<true><<<g3, 256, SMEM_K3>>>(xa, 16, out, byp_w, byp_b, proj_w, proj_b, 3);
}

// round 10
// speedup vs baseline: 1.0152x; 1.0152x over previous
#include <cuda_runtime.h>
#include <cuda_bf16.h>
#include <math.h>

#define BB 4
#define CIN 3
#define CC 32
#define HH 256
#define WW 256
#define MM 16
#define NB 4
#define OC 4
#define PIX (HH*WW)
#define GSTR 260
#define HSTR 258

typedef unsigned long long ull;

__device__ __forceinline__ ull pk2(float lo, float hi) {
    ull r; asm("mov.b64 %0,{%1,%2};" : "=l"(r) : "f"(lo), "f"(hi)); return r;
}
__device__ __forceinline__ void up2(ull v, float& a, float& b) {
    asm("mov.b64 {%0,%1},%2;" : "=f"(a), "=f"(b) : "l"(v));
}
__device__ __forceinline__ ull fma2(ull a, ull b, ull c) {
    ull d; asm("fma.rn.f32x2 %0,%1,%2,%3;" : "=l"(d) : "l"(a), "l"(b), "l"(c)); return d;
}
__device__ __forceinline__ ull mul2(ull a, ull b) {
    ull d; asm("mul.rn.f32x2 %0,%1,%2;" : "=l"(d) : "l"(a), "l"(b)); return d;
}
__device__ __forceinline__ ull neg2(ull a) { return a ^ 0x8000000080000000ULL; }

// GELU with fast erf (Abramowitz-Stegun 7.1.26, |abs err| <= 1.5e-7)
__device__ __forceinline__ float gelu1(float v) {
    float z  = v * 0.70710678118654752f;
    float az = fabsf(z);
    float t  = __fdividef(1.f, fmaf(0.3275911f, az, 1.f));
    float p  = fmaf(t, 1.061405429f, -1.453152027f);
    p = fmaf(t, p, 1.421413741f);
    p = fmaf(t, p, -0.284496736f);
    p = fmaf(t, p, 0.254829592f);
    p = p * t;
    float e  = __expf(-z * z);
    float er = fmaf(-p, e, 1.f);
    er = copysignf(er, z);
    return 0.5f * v * (1.f + er);
}

// Scratch (device globals: allocation-free)
__device__ float  g_x0[BB*CC*PIX];
__device__ float  g_xa[OC*BB*CC*PIX];
__device__ float  g_xb[OC*BB*CC*PIX];
__device__ float2 g_S [OC*BB*MM*HH*CC];            // [boh][m][h][c]
__device__ float2 g_X [OC*BB*CC*MM*MM];
__device__ float2 g_X0[BB*CC*MM*MM];
__device__ float2 g_Y [OC*BB*CC*MM*MM];
__device__ float2 g_W [OC*NB*MM*MM*CC*CC];         // [ohn][kl][c][o]
__device__ float2 g_tw2[256];

__global__ void init_tw() {
    int t = threadIdx.x;
    double a = 6.283185307179586476925286766559 * (double)t / 256.0;
    g_tw2[t] = make_float2((float)cos(a), (float)sin(a));
}

__global__ void init_w(const float* __restrict__ wr, const float* __restrict__ wi) {
    long d = (long)blockIdx.x * blockDim.x + threadIdx.x;
    int o   = (int)(d & 31);
    int c   = (int)((d >> 5) & 31);
    int kl  = (int)((d >> 10) & 255);
    int ohn = (int)(d >> 18);
    int k = kl >> 4, l = kl & 15;
    long s = ((((long)ohn * 32 + c) * 32 + o) * 16 + k) * 16 + l;
    g_W[d] = make_float2(wr[s], wi[s]);
}

__global__ void klift(const float* __restrict__ x, const float* __restrict__ lw,
                      const float* __restrict__ lb) {
    int idx = blockIdx.x * 256 + threadIdx.x;
    int pix = idx & (PIX - 1);
    int bc  = idx >> 16;
    int c = bc & 31, b = bc >> 5;
    float acc = lb[c];
    #pragma unroll
    for (int i = 0; i < CIN; i++)
        acc = fmaf(x[(b * CIN + i) * PIX + pix], lw[c * CIN + i], acc);
    g_x0[idx] = acc;
}

// K1 (once): packed W-axis truncated DFT of x0 -> S[b][m][h][c]
__global__ void k1(const float* __restrict__ xin) {
    __shared__ __align__(16) float xs[32 * GSTR];
    __shared__ float2 tws[256];
    int row0 = blockIdx.x * 32;
    for (int i = threadIdx.x; i < 8192; i += 256)
        xs[(i >> 8) * GSTR + (i & 255)] = xin[(long)row0 * 256 + i];
    tws[threadIdx.x] = g_tw2[threadIdx.x];
    __syncthreads();
    int b = row0 >> 13, c = (row0 >> 8) & 31, h0 = row0 & 255;
    int m = threadIdx.x >> 4, hh = threadIdx.x & 15;
    float sgn = (m & 1) ? -1.f : 1.f;
    ull sgn2 = pk2(sgn, sgn);
    float2 tm = tws[m], st = tws[(2 * m) & 255];
    ull cs = pk2(st.x, st.x), ss = pk2(st.y, st.y), nss = neg2(ss);
    ull c0 = pk2(1.f, tm.x), s0 = pk2(0.f, tm.y);
    ull arA = 0, asA = 0, arB = 0, asB = 0;
    const float* xr0 = xs + hh * GSTR;
    const float* xr1 = xs + (hh + 16) * GSTR;
    #pragma unroll 4
    for (int w = 0; w < 128; w += 2) {
        ull A0 = *(const ull*)(xr0 + w), B0 = *(const ull*)(xr0 + w + 128);
        ull A1 = *(const ull*)(xr1 + w), B1 = *(const ull*)(xr1 + w + 128);
        ull u0 = fma2(sgn2, B0, A0), u1 = fma2(sgn2, B1, A1);
        arA = fma2(u0, c0, arA); asA = fma2(u0, s0, asA);
        arB = fma2(u1, c0, arB); asB = fma2(u1, s0, asB);
        ull cn = fma2(c0, cs, mul2(s0, nss));
        s0 = fma2(s0, cs, mul2(c0, ss)); c0 = cn;
    }
    float a, q;
    up2(arA, a, q); float ar = a + q; up2(asA, a, q); float ai = -(a + q);
    g_S[(((long)(b * 16 + m) * 256) + h0 + hh) * 32 + c] = make_float2(ar, ai);
    up2(arB, a, q); ar = a + q; up2(asB, a, q); ai = -(a + q);
    g_S[(((long)(b * 16 + m) * 256) + h0 + hh + 16) * 32 + c] = make_float2(ar, ai);
}

// K2a: packed H-axis truncated DFT (+1/256). grid(16 l, ng, 2 chalf), 256 thr.
__global__ void k2a(const float2* __restrict__ S, float2* __restrict__ X) {
    __shared__ __align__(16) float Sre[16 * HSTR];
    __shared__ __align__(16) float Sim[16 * HSTR];
    __shared__ float2 tws[256];
    int l = blockIdx.x, g = blockIdx.y, ch = blockIdx.z;
    const float2* Sp = S + ((long)(g * 16 + l) * 256) * 32 + ch * 16;
    for (int i = threadIdx.x; i < 4096; i += 256) {
        int hh = i >> 4, cc = i & 15;
        float2 v = Sp[hh * 32 + cc];
        Sre[cc * HSTR + hh] = v.x; Sim[cc * HSTR + hh] = v.y;
    }
    tws[threadIdx.x] = g_tw2[threadIdx.x];
    __syncthreads();
    int c16 = threadIdx.x & 15, k = threadIdx.x >> 4;
    float sgn = (k & 1) ? -1.f : 1.f;
    ull sgn2 = pk2(sgn, sgn);
    float2 tk = tws[k], st = tws[(2 * k) & 255];
    ull cs = pk2(st.x, st.x), ss = pk2(st.y, st.y), nss = neg2(ss);
    ull c0 = pk2(1.f, tk.x), s0 = pk2(0.f, tk.y);
    ull arA = 0, arB = 0, aiA = 0, aiB = 0;
    const float* re = Sre + c16 * HSTR;
    const float* im = Sim + c16 * HSTR;
    #pragma unroll 4
    for (int hq = 0; hq < 128; hq += 2) {
        ull rA = *(const ull*)(re + hq), rB = *(const ull*)(re + hq + 128);
        ull iA = *(const ull*)(im + hq), iB = *(const ull*)(im + hq + 128);
        ull ux = fma2(sgn2, rB, rA), uy = fma2(sgn2, iB, iA);
        arA = fma2(ux, c0, arA); arB = fma2(uy, s0, arB);
        aiA = fma2(uy, c0, aiA); aiB = fma2(ux, s0, aiB);
        ull cn = fma2(c0, cs, mul2(s0, nss));
        s0 = fma2(s0, cs, mul2(c0, ss)); c0 = cn;
    }
    float a, q;
    up2(arA, a, q); float ar = a + q; up2(arB, a, q); ar += a + q;
    up2(aiA, a, q); float ai = a + q; up2(aiB, a, q); ai -= a + q;
    X[((long)(g * 32 + ch * 16 + c16)) * 256 + k * 16 + l] =
        make_float2(ar * (1.f / 256.f), ai * (1.f / 256.f));
}

// K2b: channel mix. grid(256 kl, OC oh), 128 thr.
__global__ void k2b(const float2* __restrict__ X, int x_oh_mult, int n) {
    __shared__ float2 Ws[32 * 32];
    __shared__ float2 Xs[4][32];
    int kl = blockIdx.x, oh = blockIdx.y;
    const float2* Wt = g_W + ((long)(oh * NB + n) * 256 + kl) * 1024;
    for (int i = threadIdx.x; i < 1024; i += 128) Ws[i] = Wt[i];
    {
        int b = threadIdx.x >> 5, c = threadIdx.x & 31;
        Xs[b][c] = X[((long)((oh * x_oh_mult + b) * 32 + c)) * 256 + kl];
    }
    __syncthreads();
    int b = threadIdx.x >> 5, o = threadIdx.x & 31;
    float yr = 0.f, yi = 0.f;
    #pragma unroll
    for (int c0 = 0; c0 < 32; c0++) {
        float2 xv = Xs[b][c0];
        float2 wv = Ws[c0 * 32 + o];
        yr += xv.x * wv.x - xv.y * wv.y;
        yi += xv.x * wv.y + xv.y * wv.x;
    }
    g_Y[((long)((oh * 4 + b) * 32 + o)) * 256 + kl] = make_float2(yr, yi);
}

// K3: H-inverse + packed W-inverse + packed bypass + GELU,
// then (LAST ? projection : next-iteration packed W-DFT)
// Dynamic smem layout (51840 B):
//   gs    [0,      33280)  float  32*GSTR
//   Bs2   [33280,  41472)  ulonglong2 32*16
//   bwT2  [41472,  49664)  ull 32*32 (replicated packs)
//   tws   [49664,  51712)  float2 256
//   pws   [51712,  51840)  float 32
#define SMEM_K3 51840
template <bool LAST>
__global__ void __launch_bounds__(256, 3) k3(
    const float* __restrict__ xin, int in_nb, float* __restrict__ xout,
    const float* __restrict__ byp_w, const float* __restrict__ byp_b,
    const float* __restrict__ pw, const float* __restrict__ pb, int n) {
    extern __shared__ __align__(16) char smemraw[];
    float*      gs   = (float*)smemraw;
    ulonglong2* Bs2  = (ulonglong2*)(smemraw + 33280);
    ull*        bwT2 = (ull*)(smemraw + 41472);
    float2*     tws  = (float2*)(smemraw + 49664);
    float*      pws  = (float*)(smemraw + 51712);
    int h = blockIdx.x, boh = blockIdx.y;
    int b = boh & 3, oh = boh >> 2;
    int ohn = oh * NB + n;
    int t = threadIdx.x;

    tws[t] = g_tw2[t];
    {   // bypass weights [o][i] -> [i][o], replicated f32x2 packs
        const float* bwp = byp_w + ohn * 1024;
        #pragma unroll
        for (int r = 0; r < 4; r++) {
            int idx = t + r * 256;
            float v = bwp[idx];
            bwT2[(idx & 31) * 32 + (idx >> 5)] = pk2(v, v);
        }
    }
    if (LAST && t < 32) pws[t] = pw[t];
    __syncthreads();

    // Phase B: H-inverse of Y; store scaled, imag-negated, replicated
    {
        const float* bbp = byp_b + ohn * 32;
        const float2* Yb = g_Y + (long)boh * 8192;
        #pragma unroll
        for (int rep = 0; rep < 2; rep++) {
            int idx = t + rep * 256;
            int o = idx >> 4, l = idx & 15;
            float br = 0.f, bi = 0.f;
            #pragma unroll
            for (int k = 0; k < 16; k++) {
                float2 y = Yb[o * 256 + k * 16 + l];
                float2 tw = tws[(k * h) & 255];
                br += y.x * tw.x - y.y * tw.y;
                bi += y.x * tw.y + y.y * tw.x;
            }
            float sc = (l == 0) ? (1.f / 256.f) : (2.f / 256.f);
            br *= sc; bi *= -sc;
            if (l == 0) br += bbp[o];          // fold bias; DC imag dropped (C2R)
            Bs2[idx] = make_ulonglong2(pk2(br, br), pk2(bi, bi));
        }
    }
    __syncthreads();

    // Phase C: thread = (og, wg): 8 o x 4 w register tile, f32x2 packed
    {
        int wg = t & 63, og = t >> 6;
        int w0 = wg * 4, o0 = og * 8;
        float2 t0 = tws[w0], t1 = tws[w0 + 1], t2 = tws[w0 + 2], t3 = tws[w0 + 3];
        ull csA = pk2(t0.x, t1.x), ssA = pk2(t0.y, t1.y), nssA = neg2(ssA);
        ull csB = pk2(t2.x, t3.x), ssB = pk2(t2.y, t3.y), nssB = neg2(ssB);
        ull accA[8], accB[8];
        #pragma unroll
        for (int oo = 0; oo < 8; oo++) {
            ull v = Bs2[(o0 + oo) * 16].x;
            accA[oo] = v; accB[oo] = v;
        }
        // spectral sum over l (trig by packed recurrence)
        ull cA = csA, sA = ssA, cB = csB, sB = ssB;
        #pragma unroll 5
        for (int l = 1; l < 16; l++) {
            #pragma unroll
            for (int oo = 0; oo < 8; oo++) {
                ulonglong2 Bv = Bs2[(o0 + oo) * 16 + l];
                accA[oo] = fma2(Bv.x, cA, accA[oo]);
                accA[oo] = fma2(Bv.y, sA, accA[oo]);
                accB[oo] = fma2(Bv.x, cB, accB[oo]);
                accB[oo] = fma2(Bv.y, sB, accB[oo]);
            }
            ull cn = fma2(cA, csA, mul2(sA, nssA));
            sA = fma2(sA, csA, mul2(cA, ssA)); cA = cn;
            cn = fma2(cB, csB, mul2(sB, nssB));
            sB = fma2(sB, csB, mul2(cB, ssB)); cB = cn;
        }
        // bypass conv: x via coalesced LDG.128, weights via broadcast LDS.128
        int inb = (in_nb == 4) ? b : boh;
        const float* xrow = xin + (((long)inb * 32) << 16) + (h << 8) + w0;
        #pragma unroll 8
        for (int i = 0; i < 32; i++) {
            float4 xv = *(const float4*)(xrow + ((long)i << 16));
            ull xA = pk2(xv.x, xv.y), xB = pk2(xv.z, xv.w);
            const ulonglong2* wp = (const ulonglong2*)(bwT2 + i * 32 + o0);
            ulonglong2 wq0 = wp[0], wq1 = wp[1], wq2 = wp[2], wq3 = wp[3];
            accA[0] = fma2(wq0.x, xA, accA[0]); accB[0] = fma2(wq0.x, xB, accB[0]);
            accA[1] = fma2(wq0.y, xA, accA[1]); accB[1] = fma2(wq0.y, xB, accB[1]);
            accA[2] = fma2(wq1.x, xA, accA[2]); accB[2] = fma2(wq1.x, xB, accB[2]);
            accA[3] = fma2(wq1.y, xA, accA[3]); accB[3] = fma2(wq1.y, xB, accB[3]);
            accA[4] = fma2(wq2.x, xA, accA[4]); accB[4] = fma2(wq2.x, xB, accB[4]);
            accA[5] = fma2(wq2.y, xA, accA[5]); accB[5] = fma2(wq2.y, xB, accB[5]);
            accA[6] = fma2(wq3.x, xA, accA[6]); accB[6] = fma2(wq3.x, xB, accB[6]);
            accA[7] = fma2(wq3.y, xA, accA[7]); accB[7] = fma2(wq3.y, xB, accB[7]);
        }
        // GELU + stores
        #pragma unroll
        for (int oo = 0; oo < 8; oo++) {
            float v0, v1, v2, v3;
            up2(accA[oo], v0, v1); up2(accB[oo], v2, v3);
            float4 gv = make_float4(gelu1(v0), gelu1(v1), gelu1(v2), gelu1(v3));
            *(float4*)(gs + (o0 + oo) * GSTR + w0) = gv;
            if (!LAST)
                *(float4*)(xout + (((long)(boh * 32 + o0 + oo)) << 16) + (h << 8) + w0) = gv;
        }
    }
    __syncthreads();

    if (!LAST) {
        // Phase D: next-iteration packed W-DFT -> S[boh][m][h][c=o]
        int o = t & 31, mp = t >> 5;                // m = mp, mp+8
        float sgn = (mp & 1) ? -1.f : 1.f;
        ull sgn2 = pk2(sgn, sgn);
        float2 tm = tws[mp], tm1 = tws[mp + 8];
        float2 st = tws[(2 * mp) & 255], st1 = tws[(2 * (mp + 8)) & 255];
        ull cs = pk2(st.x, st.x), ss = pk2(st.y, st.y), nss = neg2(ss);
        ull cs1 = pk2(st1.x, st1.x), ss1 = pk2(st1.y, st1.y), nss1 = neg2(ss1);
        ull cM = pk2(1.f, tm.x), sM = pk2(0.f, tm.y);
        ull cM1 = pk2(1.f, tm1.x), sM1 = pk2(0.f, tm1.y);
        ull ar0 = 0, as0 = 0, ar1 = 0, as1 = 0;
        const float* go = gs + o * GSTR;
        #pragma unroll 4
        for (int w = 0; w < 128; w += 2) {
            ull A = *(const ull*)(go + w);
            ull Bv = *(const ull*)(go + w + 128);
            ull u = fma2(sgn2, Bv, A);
            ar0 = fma2(u, cM, ar0); as0 = fma2(u, sM, as0);
            ar1 = fma2(u, cM1, ar1); as1 = fma2(u, sM1, as1);
            ull cn = fma2(cM, cs, mul2(sM, nss));
            sM = fma2(sM, cs, mul2(cM, ss)); cM = cn;
            cn = fma2(cM1, cs1, mul2(sM1, nss1));
            sM1 = fma2(sM1, cs1, mul2(cM1, ss1)); cM1 = cn;
        }
        float a, q;
        up2(ar0, a, q); float ar = a + q; up2(as0, a, q); float ai = -(a + q);
        g_S[(((long)(boh * 16 + mp) * 256) + h) * 32 + o] = make_float2(ar, ai);
        up2(ar1, a, q); ar = a + q; up2(as1, a, q); ai = -(a + q);
        g_S[(((long)(boh * 16 + mp + 8) * 256) + h) * 32 + o] = make_float2(ar, ai);
    } else {
        // projection
        float pacc = 0.f;
        #pragma unroll
        for (int o = 0; o < 32; o++)
            pacc = fmaf(gs[o * GSTR + t], pws[o], pacc);
        xout[(((long)(b * OC + oh) * 256 + h) << 8) + t] = pacc + pb[0];
    }
}

extern "C" void kernel_launch(void* const* d_in, const int* in_sizes, int n_in,
                              void* d_out, int out_size) {
    const float* x      = (const float*)d_in[0];
    const float* lift_w = (const float*)d_in[1];
    const float* lift_b = (const float*)d_in[2];
    const float* wr     = (const float*)d_in[3];
    const float* wi     = (const float*)d_in[4];
    const float* byp_w  = (const float*)d_in[5];
    const float* byp_b  = (const float*)d_in[6];
    const float* proj_w = (const float*)d_in[7];
    const float* proj_b = (const float*)d_in[8];
    float* out = (float*)d_out;

    float *x0, *xa, *xb;
    float2 *S, *X, *X0;
    cudaGetSymbolAddress((void**)&x0, g_x0);
    cudaGetSymbolAddress((void**)&xa, g_xa);
    cudaGetSymbolAddress((void**)&xb, g_xb);
    cudaGetSymbolAddress((void**)&S,  g_S);
    cudaGetSymbolAddress((void**)&X,  g_X);
    cudaGetSymbolAddress((void**)&X0, g_X0);

    cudaFuncSetAttribute(k3<false>, cudaFuncAttributeMaxDynamicSharedMemorySize, SMEM_K3);
    cudaFuncSetAttribute(k3<true>,  cudaFuncAttributeMaxDynamicSharedMemorySize, SMEM_K3);

    init_tw<<<1, 256>>>();
    init_w<<<4096, 1024>>>(wr, wi);
    klift<<<(BB * CC * PIX) / 256, 256>>>(x, lift_w, lift_b);
    k1<<<1024, 256>>>(x0);                          // S(x0)
    k2a<<<dim3(16, 4, 2), 256>>>(S, X0);            // X(x0), shared across oh

    dim3 g3(256, 16);
    // n = 0 (all oh concurrent)
    k2b<<<dim3(256, OC), 128>>>(X0, 0, 0);
    k3<false><<<g3, 256, SMEM_K3>>>(x0, 4, xa, byp_w, byp_b, proj_w, proj_b, 0);
    // n = 1
    k2a<<<dim3(16, 16, 2), 256>>>(S, X);
    k2b<<<dim3(256, OC), 128>>>(X, 4, 1);
    k3<false><<<g3, 256, SMEM_K3>>>(xa, 16, xb, byp_w, byp_b, proj_w, proj_b, 1);
    // n = 2
    k2a<<<dim3(16, 16, 2), 256>>>(S, X);
    k2b<<<dim3(256, OC), 128>>>(X, 4, 2);
    k3<false><<<g3, 256, SMEM_K3>>>(xb, 16, xa, byp_w, byp_b, proj_w, proj_b, 2);
    // n = 3 (fused projection)
    k2a<<<dim3(16, 16, 2), 256>>>(S, X);
    k2b<<<dim3(256, OC), 128>>>(X, 4, 3);
    k3<true><<<g3, 256, SMEM_K3>>>(xa, 16, out, byp_w, byp_b, proj_w, proj_b, 3);
}

// round 11
// speedup vs baseline: 1.1350x; 1.1180x over previous
#include <cuda_runtime.h>
#include <cuda_bf16.h>
#include <math.h>

#define BB 4
#define CIN 3
#define CC 32
#define HH 256
#define WW 256
#define MM 16
#define NB 4
#define OC 4
#define PIX (HH*WW)
#define GSTR 260
#define HSTR 258

typedef unsigned long long ull;

__device__ __forceinline__ ull pk2(float lo, float hi) {
    ull r; asm("mov.b64 %0,{%1,%2};" : "=l"(r) : "f"(lo), "f"(hi)); return r;
}
__device__ __forceinline__ void up2(ull v, float& a, float& b) {
    asm("mov.b64 {%0,%1},%2;" : "=f"(a), "=f"(b) : "l"(v));
}
__device__ __forceinline__ ull fma2(ull a, ull b, ull c) {
    ull d; asm("fma.rn.f32x2 %0,%1,%2,%3;" : "=l"(d) : "l"(a), "l"(b), "l"(c)); return d;
}
__device__ __forceinline__ ull mul2(ull a, ull b) {
    ull d; asm("mul.rn.f32x2 %0,%1,%2;" : "=l"(d) : "l"(a), "l"(b)); return d;
}
__device__ __forceinline__ ull add2(ull a, ull b) {
    ull d; asm("add.rn.f32x2 %0,%1,%2;" : "=l"(d) : "l"(a), "l"(b)); return d;
}
__device__ __forceinline__ ull neg2(ull a) { return a ^ 0x8000000080000000ULL; }

// GELU with fast erf (Abramowitz-Stegun 7.1.26, |abs err| <= 1.5e-7)
__device__ __forceinline__ float gelu1(float v) {
    float z  = v * 0.70710678118654752f;
    float az = fabsf(z);
    float t  = __fdividef(1.f, fmaf(0.3275911f, az, 1.f));
    float p  = fmaf(t, 1.061405429f, -1.453152027f);
    p = fmaf(t, p, 1.421413741f);
    p = fmaf(t, p, -0.284496736f);
    p = fmaf(t, p, 0.254829592f);
    p = p * t;
    float e  = __expf(-z * z);
    float er = fmaf(-p, e, 1.f);
    er = copysignf(er, z);
    return 0.5f * v * (1.f + er);
}

// Scratch (device globals: allocation-free)
__device__ float  g_x0[BB*CC*PIX];
__device__ float  g_xa[OC*BB*CC*PIX];
__device__ float  g_xb[OC*BB*CC*PIX];
__device__ float2 g_S [OC*BB*MM*HH*CC];            // [boh][m][h][c]
__device__ float2 g_X [OC*BB*CC*MM*MM];
__device__ float2 g_X0[BB*CC*MM*MM];
__device__ float2 g_Y [OC*BB*CC*MM*MM];
__device__ float2 g_W [OC*NB*MM*MM*CC*CC];         // [ohn][kl][c][o]
__device__ float2 g_tw2[256];

__global__ void init_tw() {
    int t = threadIdx.x;
    double a = 6.283185307179586476925286766559 * (double)t / 256.0;
    g_tw2[t] = make_float2((float)cos(a), (float)sin(a));
}

__global__ void init_w(const float* __restrict__ wr, const float* __restrict__ wi) {
    long d = (long)blockIdx.x * blockDim.x + threadIdx.x;
    int o   = (int)(d & 31);
    int c   = (int)((d >> 5) & 31);
    int kl  = (int)((d >> 10) & 255);
    int ohn = (int)(d >> 18);
    int k = kl >> 4, l = kl & 15;
    long s = ((((long)ohn * 32 + c) * 32 + o) * 16 + k) * 16 + l;
    g_W[d] = make_float2(wr[s], wi[s]);
}

__global__ void klift(const float* __restrict__ x, const float* __restrict__ lw,
                      const float* __restrict__ lb) {
    int idx = blockIdx.x * 256 + threadIdx.x;
    int pix = idx & (PIX - 1);
    int bc  = idx >> 16;
    int c = bc & 31, b = bc >> 5;
    float acc = lb[c];
    #pragma unroll
    for (int i = 0; i < CIN; i++)
        acc = fmaf(x[(b * CIN + i) * PIX + pix], lw[c * CIN + i], acc);
    g_x0[idx] = acc;
}

// K1 (once): packed W-axis truncated DFT of x0 -> S[b][m][h][c]
__global__ void k1(const float* __restrict__ xin) {
    __shared__ __align__(16) float xs[32 * GSTR];
    __shared__ float2 tws[256];
    int row0 = blockIdx.x * 32;
    for (int i = threadIdx.x; i < 8192; i += 256)
        xs[(i >> 8) * GSTR + (i & 255)] = xin[(long)row0 * 256 + i];
    tws[threadIdx.x] = g_tw2[threadIdx.x];
    __syncthreads();
    int b = row0 >> 13, c = (row0 >> 8) & 31, h0 = row0 & 255;
    int m = threadIdx.x >> 4, hh = threadIdx.x & 15;
    float sgn = (m & 1) ? -1.f : 1.f;
    ull sgn2 = pk2(sgn, sgn);
    float2 tm = tws[m], st = tws[(2 * m) & 255];
    ull cs = pk2(st.x, st.x), ss = pk2(st.y, st.y), nss = neg2(ss);
    ull c0 = pk2(1.f, tm.x), s0 = pk2(0.f, tm.y);
    ull arA = 0, asA = 0, arB = 0, asB = 0;
    const float* xr0 = xs + hh * GSTR;
    const float* xr1 = xs + (hh + 16) * GSTR;
    #pragma unroll 4
    for (int w = 0; w < 128; w += 2) {
        ull A0 = *(const ull*)(xr0 + w), B0 = *(const ull*)(xr0 + w + 128);
        ull A1 = *(const ull*)(xr1 + w), B1 = *(const ull*)(xr1 + w + 128);
        ull u0 = fma2(sgn2, B0, A0), u1 = fma2(sgn2, B1, A1);
        arA = fma2(u0, c0, arA); asA = fma2(u0, s0, asA);
        arB = fma2(u1, c0, arB); asB = fma2(u1, s0, asB);
        ull cn = fma2(c0, cs, mul2(s0, nss));
        s0 = fma2(s0, cs, mul2(c0, ss)); c0 = cn;
    }
    float a, q;
    up2(arA, a, q); float ar = a + q; up2(asA, a, q); float ai = -(a + q);
    g_S[(((long)(b * 16 + m) * 256) + h0 + hh) * 32 + c] = make_float2(ar, ai);
    up2(arB, a, q); ar = a + q; up2(asB, a, q); ai = -(a + q);
    g_S[(((long)(b * 16 + m) * 256) + h0 + hh + 16) * 32 + c] = make_float2(ar, ai);
}

// K2a: packed H-axis truncated DFT (+1/256). grid(16 l, ng, 2 chalf), 256 thr.
__global__ void k2a(const float2* __restrict__ S, float2* __restrict__ X) {
    __shared__ __align__(16) float Sre[16 * HSTR];
    __shared__ __align__(16) float Sim[16 * HSTR];
    __shared__ float2 tws[256];
    int l = blockIdx.x, g = blockIdx.y, ch = blockIdx.z;
    const float2* Sp = S + ((long)(g * 16 + l) * 256) * 32 + ch * 16;
    for (int i = threadIdx.x; i < 4096; i += 256) {
        int hh = i >> 4, cc = i & 15;
        float2 v = Sp[hh * 32 + cc];
        Sre[cc * HSTR + hh] = v.x; Sim[cc * HSTR + hh] = v.y;
    }
    tws[threadIdx.x] = g_tw2[threadIdx.x];
    __syncthreads();
    int c16 = threadIdx.x & 15, k = threadIdx.x >> 4;
    float sgn = (k & 1) ? -1.f : 1.f;
    ull sgn2 = pk2(sgn, sgn);
    float2 tk = tws[k], st = tws[(2 * k) & 255];
    ull cs = pk2(st.x, st.x), ss = pk2(st.y, st.y), nss = neg2(ss);
    ull c0 = pk2(1.f, tk.x), s0 = pk2(0.f, tk.y);
    ull arA = 0, arB = 0, aiA = 0, aiB = 0;
    const float* re = Sre + c16 * HSTR;
    const float* im = Sim + c16 * HSTR;
    #pragma unroll 4
    for (int hq = 0; hq < 128; hq += 2) {
        ull rA = *(const ull*)(re + hq), rB = *(const ull*)(re + hq + 128);
        ull iA = *(const ull*)(im + hq), iB = *(const ull*)(im + hq + 128);
        ull ux = fma2(sgn2, rB, rA), uy = fma2(sgn2, iB, iA);
        arA = fma2(ux, c0, arA); arB = fma2(uy, s0, arB);
        aiA = fma2(uy, c0, aiA); aiB = fma2(ux, s0, aiB);
        ull cn = fma2(c0, cs, mul2(s0, nss));
        s0 = fma2(s0, cs, mul2(c0, ss)); c0 = cn;
    }
    float a, q;
    up2(arA, a, q); float ar = a + q; up2(arB, a, q); ar += a + q;
    up2(aiA, a, q); float ai = a + q; up2(aiB, a, q); ai -= a + q;
    X[((long)(g * 32 + ch * 16 + c16)) * 256 + k * 16 + l] =
        make_float2(ar * (1.f / 256.f), ai * (1.f / 256.f));
}

// K2b: channel mix. grid(256 kl, OC oh), 128 thr.
__global__ void k2b(const float2* __restrict__ X, int x_oh_mult, int n) {
    __shared__ float2 Ws[32 * 32];
    __shared__ float2 Xs[4][32];
    int kl = blockIdx.x, oh = blockIdx.y;
    const float2* Wt = g_W + ((long)(oh * NB + n) * 256 + kl) * 1024;
    for (int i = threadIdx.x; i < 1024; i += 128) Ws[i] = Wt[i];
    {
        int b = threadIdx.x >> 5, c = threadIdx.x & 31;
        Xs[b][c] = X[((long)((oh * x_oh_mult + b) * 32 + c)) * 256 + kl];
    }
    __syncthreads();
    int b = threadIdx.x >> 5, o = threadIdx.x & 31;
    float yr = 0.f, yi = 0.f;
    #pragma unroll
    for (int c0 = 0; c0 < 32; c0++) {
        float2 xv = Xs[b][c0];
        float2 wv = Ws[c0 * 32 + o];
        yr += xv.x * wv.x - xv.y * wv.y;
        yi += xv.x * wv.y + xv.y * wv.x;
    }
    g_Y[((long)((oh * 4 + b) * 32 + o)) * 256 + kl] = make_float2(yr, yi);
}

// K3: H-inverse + folded half-spectrum W-inverse + packed bypass + GELU,
// then (LAST ? projection : next-iteration packed W-DFT)
template <bool LAST>
__global__ void __launch_bounds__(256, 3) k3(
    const float* __restrict__ xin, int in_nb, float* __restrict__ xout,
    const float* __restrict__ byp_w, const float* __restrict__ byp_b,
    const float* __restrict__ pw, const float* __restrict__ pb, int n) {
    __shared__ __align__(16) float gs[32 * GSTR];      // 33280B
    __shared__ __align__(16) ulonglong2 Bs2[32 * 16];  // 8192B (Br2, -Bi2) pre-scaled
    __shared__ __align__(16) float bwT[32 * 32];       // [i][o] 4096B
    __shared__ float2 tws[256];                        // 2048B
    __shared__ float pws[32];
    int h = blockIdx.x, boh = blockIdx.y;
    int b = boh & 3, oh = boh >> 2;
    int ohn = oh * NB + n;
    int t = threadIdx.x;

    tws[t] = g_tw2[t];
    {   // transpose bypass weights [o][i] -> [i][o]
        const float* bwp = byp_w + ohn * 1024;
        #pragma unroll
        for (int r = 0; r < 4; r++) {
            int idx = t + r * 256;
            bwT[(idx & 31) * 32 + (idx >> 5)] = bwp[idx];
        }
    }
    if (LAST && t < 32) pws[t] = pw[t];
    __syncthreads();

    // Phase B: H-inverse of Y; store scaled, imag-negated, replicated
    {
        const float* bbp = byp_b + ohn * 32;
        const float2* Yb = g_Y + (long)boh * 8192;
        #pragma unroll
        for (int rep = 0; rep < 2; rep++) {
            int idx = t + rep * 256;
            int o = idx >> 4, l = idx & 15;
            float br = 0.f, bi = 0.f;
            #pragma unroll
            for (int k = 0; k < 16; k++) {
                float2 y = Yb[o * 256 + k * 16 + l];
                float2 tw = tws[(k * h) & 255];
                br += y.x * tw.x - y.y * tw.y;
                bi += y.x * tw.y + y.y * tw.x;
            }
            float sc = (l == 0) ? (1.f / 256.f) : (2.f / 256.f);
            br *= sc; bi *= -sc;
            if (l == 0) br += bbp[o];          // fold bias; DC imag dropped (C2R)
            Bs2[idx] = make_ulonglong2(pk2(br, br), pk2(bi, bi));
        }
    }
    __syncthreads();

    // Phase C: thread = (og, wg): 8 o x (w0,w0+1,w0+128,w0+129) via half-spectrum fold.
    // E = DC + even-l, O = odd-l; acc(w) = E+O, acc(w+128) = E-O.
    {
        int wg = t & 63, og = t >> 6;
        int w0 = wg * 2, o0 = og * 8;
        float2 t0 = tws[w0], t1 = tws[w0 + 1];
        ull cs = pk2(t0.x, t1.x), ss = pk2(t0.y, t1.y), nss = neg2(ss);
        ull E[8], O[8];
        #pragma unroll
        for (int oo = 0; oo < 8; oo++) {
            E[oo] = Bs2[(o0 + oo) * 16].x;
            O[oo] = 0;
        }
        ull c = cs, s = ss;               // twiddle for current l (starts at l=1)
        #pragma unroll
        for (int l = 1; l < 16; l++) {
            if (l & 1) {
                #pragma unroll
                for (int oo = 0; oo < 8; oo++) {
                    ulonglong2 Bv = Bs2[(o0 + oo) * 16 + l];
                    O[oo] = fma2(Bv.x, c, O[oo]);
                    O[oo] = fma2(Bv.y, s, O[oo]);
                }
            } else {
                #pragma unroll
                for (int oo = 0; oo < 8; oo++) {
                    ulonglong2 Bv = Bs2[(o0 + oo) * 16 + l];
                    E[oo] = fma2(Bv.x, c, E[oo]);
                    E[oo] = fma2(Bv.y, s, E[oo]);
                }
            }
            if (l < 15) {
                ull cn = fma2(c, cs, mul2(s, nss));
                s = fma2(s, cs, mul2(c, ss)); c = cn;
            }
        }
        ull accA[8], accB[8];             // A = w0,w0+1 ; B = w0+128,w0+129
        #pragma unroll
        for (int oo = 0; oo < 8; oo++) {
            accA[oo] = add2(E[oo], O[oo]);
            accB[oo] = add2(E[oo], neg2(O[oo]));
        }
        // bypass conv: x via LDG.64 pairs, weights via broadcast LDS.128
        int inb = (in_nb == 4) ? b : boh;
        const float* xrow = xin + (((long)inb * 32) << 16) + (h << 8) + w0;
        #pragma unroll 8
        for (int i = 0; i < 32; i++) {
            ull xA = *(const ull*)(xrow + ((long)i << 16));
            ull xB = *(const ull*)(xrow + ((long)i << 16) + 128);
            const float4* wp = (const float4*)(bwT + i * 32 + o0);
            float4 wa = wp[0], wb = wp[1];
            float wv[8] = {wa.x, wa.y, wa.z, wa.w, wb.x, wb.y, wb.z, wb.w};
            #pragma unroll
            for (int oo = 0; oo < 8; oo++) {
                ull w2 = pk2(wv[oo], wv[oo]);
                accA[oo] = fma2(w2, xA, accA[oo]);
                accB[oo] = fma2(w2, xB, accB[oo]);
            }
        }
        // GELU + stores (two 8B stores per oo: w0 and w0+128)
        #pragma unroll
        for (int oo = 0; oo < 8; oo++) {
            float v0, v1, v2, v3;
            up2(accA[oo], v0, v1); up2(accB[oo], v2, v3);
            float2 glo = make_float2(gelu1(v0), gelu1(v1));
            float2 ghi = make_float2(gelu1(v2), gelu1(v3));
            *(float2*)(gs + (o0 + oo) * GSTR + w0)       = glo;
            *(float2*)(gs + (o0 + oo) * GSTR + w0 + 128) = ghi;
            if (!LAST) {
                float* orow = xout + (((long)(boh * 32 + o0 + oo)) << 16) + (h << 8) + w0;
                *(float2*)orow         = glo;
                *(float2*)(orow + 128) = ghi;
            }
        }
    }
    __syncthreads();

    if (!LAST) {
        // Phase D: next-iteration packed W-DFT -> S[boh][m][h][c=o]
        int o = t & 31, mp = t >> 5;                // m = mp, mp+8
        float sgn = (mp & 1) ? -1.f : 1.f;
        ull sgn2 = pk2(sgn, sgn);
        float2 tm = tws[mp], tm1 = tws[mp + 8];
        float2 st = tws[(2 * mp) & 255], st1 = tws[(2 * (mp + 8)) & 255];
        ull cs = pk2(st.x, st.x), ss = pk2(st.y, st.y), nss = neg2(ss);
        ull cs1 = pk2(st1.x, st1.x), ss1 = pk2(st1.y, st1.y), nss1 = neg2(ss1);
        ull cM = pk2(1.f, tm.x), sM = pk2(0.f, tm.y);
        ull cM1 = pk2(1.f, tm1.x), sM1 = pk2(0.f, tm1.y);
        ull ar0 = 0, as0 = 0, ar1 = 0, as1 = 0;
        const float* go = gs + o * GSTR;
        #pragma unroll 4
        for (int w = 0; w < 128; w += 2) {
            ull A = *(const ull*)(go + w);
            ull Bv = *(const ull*)(go + w + 128);
            ull u = fma2(sgn2, Bv, A);
            ar0 = fma2(u, cM, ar0); as0 = fma2(u, sM, as0);
            ar1 = fma2(u, cM1, ar1); as1 = fma2(u, sM1, as1);
            ull cn = fma2(cM, cs, mul2(sM, nss));
            sM = fma2(sM, cs, mul2(cM, ss)); cM = cn;
            cn = fma2(cM1, cs1, mul2(sM1, nss1));
            sM1 = fma2(sM1, cs1, mul2(cM1, ss1)); cM1 = cn;
        }
        float a, q;
        up2(ar0, a, q); float ar = a + q; up2(as0, a, q); float ai = -(a + q);
        g_S[(((long)(boh * 16 + mp) * 256) + h) * 32 + o] = make_float2(ar, ai);
        up2(ar1, a, q); ar = a + q; up2(as1, a, q); ai = -(a + q);
        g_S[(((long)(boh * 16 + mp + 8) * 256) + h) * 32 + o] = make_float2(ar, ai);
    } else {
        // projection
        float pacc = 0.f;
        #pragma unroll
        for (int o = 0; o < 32; o++)
            pacc = fmaf(gs[o * GSTR + t], pws[o], pacc);
        xout[(((long)(b * OC + oh) * 256 + h) << 8) + t] = pacc + pb[0];
    }
}

extern "C" void kernel_launch(void* const* d_in, const int* in_sizes, int n_in,
                              void* d_out, int out_size) {
    const float* x      = (const float*)d_in[0];
    const float* lift_w = (const float*)d_in[1];
    const float* lift_b = (const float*)d_in[2];
    const float* wr     = (const float*)d_in[3];
    const float* wi     = (const float*)d_in[4];
    const float* byp_w  = (const float*)d_in[5];
    const float* byp_b  = (const float*)d_in[6];
    const float* proj_w = (const float*)d_in[7];
    const float* proj_b = (const float*)d_in[8];
    float* out = (float*)d_out;

    float *x0, *xa, *xb;
    float2 *S, *X, *X0;
    cudaGetSymbolAddress((void**)&x0, g_x0);
    cudaGetSymbolAddress((void**)&xa, g_xa);
    cudaGetSymbolAddress((void**)&xb, g_xb);
    cudaGetSymbolAddress((void**)&S,  g_S);
    cudaGetSymbolAddress((void**)&X,  g_X);
    cudaGetSymbolAddress((void**)&X0, g_X0);

    init_tw<<<1, 256>>>();
    init_w<<<4096, 1024>>>(wr, wi);
    klift<<<(BB * CC * PIX) / 256, 256>>>(x, lift_w, lift_b);
    k1<<<1024, 256>>>(x0);                          // S(x0)
    k2a<<<dim3(16, 4, 2), 256>>>(S, X0);            // X(x0), shared across oh

    dim3 g3(256, 16);
    // n = 0 (all oh concurrent)
    k2b<<<dim3(256, OC), 128>>>(X0, 0, 0);
    k3<false><<<g3, 256>>>(x0, 4, xa, byp_w, byp_b, proj_w, proj_b, 0);
    // n = 1
    k2a<<<dim3(16, 16, 2), 256>>>(S, X);
    k2b<<<dim3(256, OC), 128>>>(X, 4, 1);
    k3<false><<<g3, 256>>>(xa, 16, xb, byp_w, byp_b, proj_w, proj_b, 1);
    // n = 2
    k2a<<<dim3(16, 16, 2), 256>>>(S, X);
    k2b<<<dim3(256, OC), 128>>>(X, 4, 2);
    k3<false><<<g3, 256>>>(xb, 16, xa, byp_w, byp_b, proj_w, proj_b, 2);
    // n = 3 (fused projection)
    k2a<<<dim3(16, 16, 2), 256>>>(S, X);
    k2b<<<dim3(256, OC), 128>>>(X, 4, 3);
    k3<true><<<g3, 256>>>(xa, 16, out, byp_w, byp_b, proj_w, proj_b, 3);
}

// round 12
// speedup vs baseline: 1.1979x; 1.0554x over previous
#include <cuda_runtime.h>
#include <cuda_bf16.h>
#include <math.h>

#define BB 4
#define CIN 3
#define CC 32
#define HH 256
#define WW 256
#define MM 16
#define NB 4
#define OC 4
#define PIX (HH*WW)
#define GSTR 260
#define HSTR 258

typedef unsigned long long ull;

__device__ __forceinline__ ull pk2(float lo, float hi) {
    ull r; asm("mov.b64 %0,{%1,%2};" : "=l"(r) : "f"(lo), "f"(hi)); return r;
}
__device__ __forceinline__ void up2(ull v, float& a, float& b) {
    asm("mov.b64 {%0,%1},%2;" : "=f"(a), "=f"(b) : "l"(v));
}
__device__ __forceinline__ ull fma2(ull a, ull b, ull c) {
    ull d; asm("fma.rn.f32x2 %0,%1,%2,%3;" : "=l"(d) : "l"(a), "l"(b), "l"(c)); return d;
}
__device__ __forceinline__ ull mul2(ull a, ull b) {
    ull d; asm("mul.rn.f32x2 %0,%1,%2;" : "=l"(d) : "l"(a), "l"(b)); return d;
}
__device__ __forceinline__ ull add2(ull a, ull b) {
    ull d; asm("add.rn.f32x2 %0,%1,%2;" : "=l"(d) : "l"(a), "l"(b)); return d;
}
__device__ __forceinline__ ull neg2(ull a) { return a ^ 0x8000000080000000ULL; }

// GELU with fast erf (Abramowitz-Stegun 7.1.26, |abs err| <= 1.5e-7)
__device__ __forceinline__ float gelu1(float v) {
    float z  = v * 0.70710678118654752f;
    float az = fabsf(z);
    float t  = __fdividef(1.f, fmaf(0.3275911f, az, 1.f));
    float p  = fmaf(t, 1.061405429f, -1.453152027f);
    p = fmaf(t, p, 1.421413741f);
    p = fmaf(t, p, -0.284496736f);
    p = fmaf(t, p, 0.254829592f);
    p = p * t;
    float e  = __expf(-z * z);
    float er = fmaf(-p, e, 1.f);
    er = copysignf(er, z);
    return 0.5f * v * (1.f + er);
}

// Scratch (device globals: allocation-free)
__device__ float  g_x0[BB*CC*PIX];
__device__ float  g_xa[OC*BB*CC*PIX];
__device__ float  g_xb[OC*BB*CC*PIX];
__device__ float2 g_S [OC*BB*MM*HH*CC];            // [boh][m][h][c]
__device__ float2 g_X [OC*BB*CC*MM*MM];
__device__ float2 g_X0[BB*CC*MM*MM];
__device__ float2 g_Y [OC*BB*CC*MM*MM];
__device__ float2 g_W [OC*NB*MM*MM*CC*CC];         // [ohn][kl][c][o]
__device__ float2 g_tw2[256];

__global__ void init_tw() {
    int t = threadIdx.x;
    double a = 6.283185307179586476925286766559 * (double)t / 256.0;
    g_tw2[t] = make_float2((float)cos(a), (float)sin(a));
}

__global__ void init_w(const float* __restrict__ wr, const float* __restrict__ wi) {
    long d = (long)blockIdx.x * blockDim.x + threadIdx.x;
    int o   = (int)(d & 31);
    int c   = (int)((d >> 5) & 31);
    int kl  = (int)((d >> 10) & 255);
    int ohn = (int)(d >> 18);
    int k = kl >> 4, l = kl & 15;
    long s = ((((long)ohn * 32 + c) * 32 + o) * 16 + k) * 16 + l;
    g_W[d] = make_float2(wr[s], wi[s]);
}

__global__ void klift(const float* __restrict__ x, const float* __restrict__ lw,
                      const float* __restrict__ lb) {
    int idx = blockIdx.x * 256 + threadIdx.x;
    int pix = idx & (PIX - 1);
    int bc  = idx >> 16;
    int c = bc & 31, b = bc >> 5;
    float acc = lb[c];
    #pragma unroll
    for (int i = 0; i < CIN; i++)
        acc = fmaf(x[(b * CIN + i) * PIX + pix], lw[c * CIN + i], acc);
    g_x0[idx] = acc;
}

// K1 (once): packed W-axis truncated DFT of x0 -> S[b][m][h][c]
__global__ void k1(const float* __restrict__ xin) {
    __shared__ __align__(16) float xs[32 * GSTR];
    __shared__ float2 tws[256];
    int row0 = blockIdx.x * 32;
    for (int i = threadIdx.x; i < 8192; i += 256)
        xs[(i >> 8) * GSTR + (i & 255)] = xin[(long)row0 * 256 + i];
    tws[threadIdx.x] = g_tw2[threadIdx.x];
    __syncthreads();
    int b = row0 >> 13, c = (row0 >> 8) & 31, h0 = row0 & 255;
    int m = threadIdx.x >> 4, hh = threadIdx.x & 15;
    float sgn = (m & 1) ? -1.f : 1.f;
    ull sgn2 = pk2(sgn, sgn);
    float2 tm = tws[m], st = tws[(2 * m) & 255];
    ull cs = pk2(st.x, st.x), ss = pk2(st.y, st.y), nss = neg2(ss);
    ull c0 = pk2(1.f, tm.x), s0 = pk2(0.f, tm.y);
    ull arA = 0, asA = 0, arB = 0, asB = 0;
    const float* xr0 = xs + hh * GSTR;
    const float* xr1 = xs + (hh + 16) * GSTR;
    #pragma unroll 4
    for (int w = 0; w < 128; w += 2) {
        ull A0 = *(const ull*)(xr0 + w), B0 = *(const ull*)(xr0 + w + 128);
        ull A1 = *(const ull*)(xr1 + w), B1 = *(const ull*)(xr1 + w + 128);
        ull u0 = fma2(sgn2, B0, A0), u1 = fma2(sgn2, B1, A1);
        arA = fma2(u0, c0, arA); asA = fma2(u0, s0, asA);
        arB = fma2(u1, c0, arB); asB = fma2(u1, s0, asB);
        ull cn = fma2(c0, cs, mul2(s0, nss));
        s0 = fma2(s0, cs, mul2(c0, ss)); c0 = cn;
    }
    float a, q;
    up2(arA, a, q); float ar = a + q; up2(asA, a, q); float ai = -(a + q);
    g_S[(((long)(b * 16 + m) * 256) + h0 + hh) * 32 + c] = make_float2(ar, ai);
    up2(arB, a, q); ar = a + q; up2(asB, a, q); ai = -(a + q);
    g_S[(((long)(b * 16 + m) * 256) + h0 + hh + 16) * 32 + c] = make_float2(ar, ai);
}

// K2a: packed H-axis truncated DFT (+1/256). grid(16 l, ng, 2 chalf), 256 thr.
__global__ void k2a(const float2* __restrict__ S, float2* __restrict__ X) {
    __shared__ __align__(16) float Sre[16 * HSTR];
    __shared__ __align__(16) float Sim[16 * HSTR];
    __shared__ float2 tws[256];
    int l = blockIdx.x, g = blockIdx.y, ch = blockIdx.z;
    const float2* Sp = S + ((long)(g * 16 + l) * 256) * 32 + ch * 16;
    for (int i = threadIdx.x; i < 4096; i += 256) {
        int hh = i >> 4, cc = i & 15;
        float2 v = Sp[hh * 32 + cc];
        Sre[cc * HSTR + hh] = v.x; Sim[cc * HSTR + hh] = v.y;
    }
    tws[threadIdx.x] = g_tw2[threadIdx.x];
    __syncthreads();
    int c16 = threadIdx.x & 15, k = threadIdx.x >> 4;
    float sgn = (k & 1) ? -1.f : 1.f;
    ull sgn2 = pk2(sgn, sgn);
    float2 tk = tws[k], st = tws[(2 * k) & 255];
    ull cs = pk2(st.x, st.x), ss = pk2(st.y, st.y), nss = neg2(ss);
    ull c0 = pk2(1.f, tk.x), s0 = pk2(0.f, tk.y);
    ull arA = 0, arB = 0, aiA = 0, aiB = 0;
    const float* re = Sre + c16 * HSTR;
    const float* im = Sim + c16 * HSTR;
    #pragma unroll 4
    for (int hq = 0; hq < 128; hq += 2) {
        ull rA = *(const ull*)(re + hq), rB = *(const ull*)(re + hq + 128);
        ull iA = *(const ull*)(im + hq), iB = *(const ull*)(im + hq + 128);
        ull ux = fma2(sgn2, rB, rA), uy = fma2(sgn2, iB, iA);
        arA = fma2(ux, c0, arA); arB = fma2(uy, s0, arB);
        aiA = fma2(uy, c0, aiA); aiB = fma2(ux, s0, aiB);
        ull cn = fma2(c0, cs, mul2(s0, nss));
        s0 = fma2(s0, cs, mul2(c0, ss)); c0 = cn;
    }
    float a, q;
    up2(arA, a, q); float ar = a + q; up2(arB, a, q); ar += a + q;
    up2(aiA, a, q); float ai = a + q; up2(aiB, a, q); ai -= a + q;
    X[((long)(g * 32 + ch * 16 + c16)) * 256 + k * 16 + l] =
        make_float2(ar * (1.f / 256.f), ai * (1.f / 256.f));
}

// K2b: channel mix. grid(256 kl, OC oh), 128 thr.
__global__ void k2b(const float2* __restrict__ X, int x_oh_mult, int n) {
    __shared__ float2 Ws[32 * 32];
    __shared__ float2 Xs[4][32];
    int kl = blockIdx.x, oh = blockIdx.y;
    const float2* Wt = g_W + ((long)(oh * NB + n) * 256 + kl) * 1024;
    for (int i = threadIdx.x; i < 1024; i += 128) Ws[i] = Wt[i];
    {
        int b = threadIdx.x >> 5, c = threadIdx.x & 31;
        Xs[b][c] = X[((long)((oh * x_oh_mult + b) * 32 + c)) * 256 + kl];
    }
    __syncthreads();
    int b = threadIdx.x >> 5, o = threadIdx.x & 31;
    float yr = 0.f, yi = 0.f;
    #pragma unroll
    for (int c0 = 0; c0 < 32; c0++) {
        float2 xv = Xs[b][c0];
        float2 wv = Ws[c0 * 32 + o];
        yr += xv.x * wv.x - xv.y * wv.y;
        yi += xv.x * wv.y + xv.y * wv.x;
    }
    g_Y[((long)((oh * 4 + b) * 32 + o)) * 256 + kl] = make_float2(yr, yi);
}

// K3: H-inverse + folded half-spectrum W-inverse + packed bypass + GELU,
// then (LAST ? projection : next-iteration radix-4 packed W-DFT)
template <bool LAST>
__global__ void __launch_bounds__(256, 3) k3(
    const float* __restrict__ xin, int in_nb, float* __restrict__ xout,
    const float* __restrict__ byp_w, const float* __restrict__ byp_b,
    const float* __restrict__ pw, const float* __restrict__ pb, int n) {
    __shared__ __align__(16) float gs[32 * GSTR];      // 33280B
    __shared__ __align__(16) ulonglong2 Bs2[32 * 16];  // 8192B (Br2, -Bi2) pre-scaled
    __shared__ __align__(16) float bwT[32 * 32];       // [i][o] 4096B
    __shared__ float2 tws[256];                        // 2048B
    __shared__ float pws[32];
    int h = blockIdx.x, boh = blockIdx.y;
    int b = boh & 3, oh = boh >> 2;
    int ohn = oh * NB + n;
    int t = threadIdx.x;

    tws[t] = g_tw2[t];
    {   // transpose bypass weights [o][i] -> [i][o]
        const float* bwp = byp_w + ohn * 1024;
        #pragma unroll
        for (int r = 0; r < 4; r++) {
            int idx = t + r * 256;
            bwT[(idx & 31) * 32 + (idx >> 5)] = bwp[idx];
        }
    }
    if (LAST && t < 32) pws[t] = pw[t];
    __syncthreads();

    // Phase B: H-inverse of Y; store scaled, imag-negated, replicated
    {
        const float* bbp = byp_b + ohn * 32;
        const float2* Yb = g_Y + (long)boh * 8192;
        #pragma unroll
        for (int rep = 0; rep < 2; rep++) {
            int idx = t + rep * 256;
            int o = idx >> 4, l = idx & 15;
            float br = 0.f, bi = 0.f;
            #pragma unroll
            for (int k = 0; k < 16; k++) {
                float2 y = Yb[o * 256 + k * 16 + l];
                float2 tw = tws[(k * h) & 255];
                br += y.x * tw.x - y.y * tw.y;
                bi += y.x * tw.y + y.y * tw.x;
            }
            float sc = (l == 0) ? (1.f / 256.f) : (2.f / 256.f);
            br *= sc; bi *= -sc;
            if (l == 0) br += bbp[o];          // fold bias; DC imag dropped (C2R)
            Bs2[idx] = make_ulonglong2(pk2(br, br), pk2(bi, bi));
        }
    }
    __syncthreads();

    // Phase C: thread = (og, wg): 8 o x (w0,w0+1,w0+128,w0+129) via half-spectrum fold.
    // E = DC + even-l, O = odd-l; acc(w) = E+O, acc(w+128) = E-O.
    {
        int wg = t & 63, og = t >> 6;
        int w0 = wg * 2, o0 = og * 8;
        float2 t0 = tws[w0], t1 = tws[w0 + 1];
        ull cs = pk2(t0.x, t1.x), ss = pk2(t0.y, t1.y), nss = neg2(ss);
        ull E[8], O[8];
        #pragma unroll
        for (int oo = 0; oo < 8; oo++) {
            E[oo] = Bs2[(o0 + oo) * 16].x;
            O[oo] = 0;
        }
        ull c = cs, s = ss;               // twiddle for current l (starts at l=1)
        #pragma unroll
        for (int l = 1; l < 16; l++) {
            if (l & 1) {
                #pragma unroll
                for (int oo = 0; oo < 8; oo++) {
                    ulonglong2 Bv = Bs2[(o0 + oo) * 16 + l];
                    O[oo] = fma2(Bv.x, c, O[oo]);
                    O[oo] = fma2(Bv.y, s, O[oo]);
                }
            } else {
                #pragma unroll
                for (int oo = 0; oo < 8; oo++) {
                    ulonglong2 Bv = Bs2[(o0 + oo) * 16 + l];
                    E[oo] = fma2(Bv.x, c, E[oo]);
                    E[oo] = fma2(Bv.y, s, E[oo]);
                }
            }
            if (l < 15) {
                ull cn = fma2(c, cs, mul2(s, nss));
                s = fma2(s, cs, mul2(c, ss)); c = cn;
            }
        }
        ull accA[8], accB[8];             // A = w0,w0+1 ; B = w0+128,w0+129
        #pragma unroll
        for (int oo = 0; oo < 8; oo++) {
            accA[oo] = add2(E[oo], O[oo]);
            accB[oo] = add2(E[oo], neg2(O[oo]));
        }
        // bypass conv: x via LDG.64 pairs, weights via broadcast LDS.128
        int inb = (in_nb == 4) ? b : boh;
        const float* xrow = xin + (((long)inb * 32) << 16) + (h << 8) + w0;
        #pragma unroll 8
        for (int i = 0; i < 32; i++) {
            ull xA = *(const ull*)(xrow + ((long)i << 16));
            ull xB = *(const ull*)(xrow + ((long)i << 16) + 128);
            const float4* wp = (const float4*)(bwT + i * 32 + o0);
            float4 wa = wp[0], wb = wp[1];
            float wv[8] = {wa.x, wa.y, wa.z, wa.w, wb.x, wb.y, wb.z, wb.w};
            #pragma unroll
            for (int oo = 0; oo < 8; oo++) {
                ull w2 = pk2(wv[oo], wv[oo]);
                accA[oo] = fma2(w2, xA, accA[oo]);
                accB[oo] = fma2(w2, xB, accB[oo]);
            }
        }
        // GELU + stores (two 8B stores per oo: w0 and w0+128)
        #pragma unroll
        for (int oo = 0; oo < 8; oo++) {
            float v0, v1, v2, v3;
            up2(accA[oo], v0, v1); up2(accB[oo], v2, v3);
            float2 glo = make_float2(gelu1(v0), gelu1(v1));
            float2 ghi = make_float2(gelu1(v2), gelu1(v3));
            *(float2*)(gs + (o0 + oo) * GSTR + w0)       = glo;
            *(float2*)(gs + (o0 + oo) * GSTR + w0 + 128) = ghi;
            if (!LAST) {
                float* orow = xout + (((long)(boh * 32 + o0 + oo)) << 16) + (h << 8) + w0;
                *(float2*)orow         = glo;
                *(float2*)(orow + 128) = ghi;
            }
        }
    }
    __syncthreads();

    if (!LAST) {
        // Phase D: radix-4 next-iteration W-DFT -> S[boh][m][h][c=o]
        // m in {mp, mp+8}; both share r = m mod 4.
        // v(w') = g0 + (-i)^m g1 + (-1)^m g2 + ((-i)^m)^3 g3 over quarters of length 64.
        // S[m] = sum_{w'=0}^{63} v(w') e^{-2pi i m w'/256}
        int o = t & 31, mp = t >> 5;                // mp in [0,8)
        int r = mp & 3;
        const float* go = gs + o * GSTR;
        float2 tm0 = tws[mp], tm1 = tws[mp + 8];
        float2 st0 = tws[(2 * mp) & 255], st1 = tws[(2 * (mp + 8)) & 255];
        ull cs0 = pk2(st0.x, st0.x), ss0 = pk2(st0.y, st0.y), nss0 = neg2(ss0);
        ull cs1 = pk2(st1.x, st1.x), ss1 = pk2(st1.y, st1.y), nss1 = neg2(ss1);
        ull c0 = pk2(1.f, tm0.x), s0 = pk2(0.f, tm0.y);
        ull c1 = pk2(1.f, tm1.x), s1 = pk2(0.f, tm1.y);
        ull negp = pk2(-1.f, -1.f);
        float a, q, ar, ai;
        float2* Sd0 = &g_S[(((long)(boh * 16 + mp) * 256) + h) * 32 + o];
        float2* Sd1 = &g_S[(((long)(boh * 16 + mp + 8) * 256) + h) * 32 + o];
        if ((r & 1) == 0) {
            // even r: v real = (g0+g2) + sigma*(g1+g3), sigma = +1 (r=0) / -1 (r=2)
            ull ar0 = 0, as0 = 0, ar1 = 0, as1 = 0;
            #pragma unroll 4
            for (int w2 = 0; w2 < 64; w2 += 2) {
                ull g0v = *(const ull*)(go + w2);
                ull g1v = *(const ull*)(go + w2 + 64);
                ull g2v = *(const ull*)(go + w2 + 128);
                ull g3v = *(const ull*)(go + w2 + 192);
                ull p02 = add2(g0v, g2v);
                ull p13 = add2(g1v, g3v);
                ull v = (r == 0) ? add2(p02, p13) : fma2(negp, p13, p02);
                ar0 = fma2(v, c0, ar0); as0 = fma2(v, s0, as0);
                ar1 = fma2(v, c1, ar1); as1 = fma2(v, s1, as1);
                ull cn = fma2(c0, cs0, mul2(s0, nss0));
                s0 = fma2(s0, cs0, mul2(c0, ss0)); c0 = cn;
                cn = fma2(c1, cs1, mul2(s1, nss1));
                s1 = fma2(s1, cs1, mul2(c1, ss1)); c1 = cn;
            }
            up2(ar0, a, q); ar = a + q; up2(as0, a, q); ai = -(a + q);
            *Sd0 = make_float2(ar, ai);
            up2(ar1, a, q); ar = a + q; up2(as1, a, q); ai = -(a + q);
            *Sd1 = make_float2(ar, ai);
        } else {
            // odd r: v = vr + i*vi, vr = g0-g2, vi = (r==1 ? g3-g1 : g1-g3)
            // S += (vr + i vi)(c - i s): ar += vr*c + vi*s ; ai += vi*c - vr*s
            ull ar0 = 0, ic0 = 0, rs0 = 0, ar1 = 0, ic1 = 0, rs1 = 0;
            #pragma unroll 4
            for (int w2 = 0; w2 < 64; w2 += 2) {
                ull g0v = *(const ull*)(go + w2);
                ull g1v = *(const ull*)(go + w2 + 64);
                ull g2v = *(const ull*)(go + w2 + 128);
                ull g3v = *(const ull*)(go + w2 + 192);
                ull vr = fma2(negp, g2v, g0v);
                ull vi = (r == 1) ? fma2(negp, g1v, g3v) : fma2(negp, g3v, g1v);
                ar0 = fma2(vr, c0, ar0); ar0 = fma2(vi, s0, ar0);
                ic0 = fma2(vi, c0, ic0); rs0 = fma2(vr, s0, rs0);
                ar1 = fma2(vr, c1, ar1); ar1 = fma2(vi, s1, ar1);
                ic1 = fma2(vi, c1, ic1); rs1 = fma2(vr, s1, rs1);
                ull cn = fma2(c0, cs0, mul2(s0, nss0));
                s0 = fma2(s0, cs0, mul2(c0, ss0)); c0 = cn;
                cn = fma2(c1, cs1, mul2(s1, nss1));
                s1 = fma2(s1, cs1, mul2(c1, ss1)); c1 = cn;
            }
            float a2, q2;
            up2(ar0, a, q); ar = a + q;
            up2(ic0, a, q); up2(rs0, a2, q2); ai = (a + q) - (a2 + q2);
            *Sd0 = make_float2(ar, ai);
            up2(ar1, a, q); ar = a + q;
            up2(ic1, a, q); up2(rs1, a2, q2); ai = (a + q) - (a2 + q2);
            *Sd1 = make_float2(ar, ai);
        }
    } else {
        // projection
        float pacc = 0.f;
        #pragma unroll
        for (int o = 0; o < 32; o++)
            pacc = fmaf(gs[o * GSTR + t], pws[o], pacc);
        xout[(((long)(b * OC + oh) * 256 + h) << 8) + t] = pacc + pb[0];
    }
}

extern "C" void kernel_launch(void* const* d_in, const int* in_sizes, int n_in,
                              void* d_out, int out_size) {
    const float* x      = (const float*)d_in[0];
    const float* lift_w = (const float*)d_in[1];
    const float* lift_b = (const float*)d_in[2];
    const float* wr     = (const float*)d_in[3];
    const float* wi     = (const float*)d_in[4];
    const float* byp_w  = (const float*)d_in[5];
    const float* byp_b  = (const float*)d_in[6];
    const float* proj_w = (const float*)d_in[7];
    const float* proj_b = (const float*)d_in[8];
    float* out = (float*)d_out;

    float *x0, *xa, *xb;
    float2 *S, *X, *X0;
    cudaGetSymbolAddress((void**)&x0, g_x0);
    cudaGetSymbolAddress((void**)&xa, g_xa);
    cudaGetSymbolAddress((void**)&xb, g_xb);
    cudaGetSymbolAddress((void**)&S,  g_S);
    cudaGetSymbolAddress((void**)&X,  g_X);
    cudaGetSymbolAddress((void**)&X0, g_X0);

    init_tw<<<1, 256>>>();
    init_w<<<4096, 1024>>>(wr, wi);
    klift<<<(BB * CC * PIX) / 256, 256>>>(x, lift_w, lift_b);
    k1<<<1024, 256>>>(x0);                          // S(x0)
    k2a<<<dim3(16, 4, 2), 256>>>(S, X0);            // X(x0), shared across oh

    dim3 g3(256, 16);
    // n = 0 (all oh concurrent)
    k2b<<<dim3(256, OC), 128>>>(X0, 0, 0);
    k3<false><<<g3, 256>>>(x0, 4, xa, byp_w, byp_b, proj_w, proj_b, 0);
    // n = 1
    k2a<<<dim3(16, 16, 2), 256>>>(S, X);
    k2b<<<dim3(256, OC), 128>>>(X, 4, 1);
    k3<false><<<g3, 256>>>(xa, 16, xb, byp_w, byp_b, proj_w, proj_b, 1);
    // n = 2
    k2a<<<dim3(16, 16, 2), 256>>>(S, X);
    k2b<<<dim3(256, OC), 128>>>(X, 4, 2);
    k3<false><<<g3, 256>>>(xb, 16, xa, byp_w, byp_b, proj_w, proj_b, 2);
    // n = 3 (fused projection)
    k2a<<<dim3(16, 16, 2), 256>>>(S, X);
    k2b<<<dim3(256, OC), 128>>>(X, 4, 3);
    k3<true><<<g3, 256>>>(xa, 16, out, byp_w, byp_b, proj_w, proj_b, 3);
}